// round 6
// baseline (speedup 1.0000x reference)
#include <cuda_runtime.h>
#include <cstdint>

#define DIMSZ   2048
#define HD      128
#define NHEADS  16
#define NKV     4
#define BSZ     4
#define SEQ     2048
#define MROWS   (BSZ*SEQ)      /* 8192 */
#define KVW     (NKV*HD)       /* 512  */
#define EPSF    1e-6f

// ---------------- scratch (static device globals; no allocation) ----------------
__device__ float g_Qn[(size_t)MROWS * DIMSZ];   // 64 MB: rmsnormed Q proj
__device__ float g_Kn[(size_t)MROWS * KVW];     // 16 MB: rmsnormed K proj
__device__ float g_Vn[(size_t)MROWS * KVW];     // 16 MB: V proj
__device__ float g_AO[(size_t)MROWS * DIMSZ];   // 64 MB: attention output

// =================================================================================
// C[M,N] = A[M,K] @ B[N,K]^T   (both row-major, K contiguous — "NT" GEMM)
// Optional epilogue: RMSNorm over each 128-wide column group (BN == HD == 128,
// so a block tile covers exactly one head's columns).
// Tiles: BM=128, BN=128, BK=16; 256 threads; 8x8 per-thread microtile.
// =================================================================================
__global__ __launch_bounds__(256)
void sgemm_nt(const float* __restrict__ A, const float* __restrict__ B,
              float* __restrict__ C, int N, int K,
              const float* __restrict__ normw)
{
    __shared__ float As[16][128];
    __shared__ float Bs[16][128];
    __shared__ float red[128][17];   // rmsnorm reduction

    const int tid = threadIdx.x;
    const int tx  = tid & 15;
    const int ty  = tid >> 4;
    const int rowBase = blockIdx.y * 128;
    const int colBase = blockIdx.x * 128;

    // loader: each thread loads 8 consecutive K-floats of one row of A and B
    const int lrow = tid >> 1;          // 0..127
    const int lcol = (tid & 1) * 8;     // 0 or 8
    const float* Ap = A + (size_t)(rowBase + lrow) * K + lcol;
    const float* Bp = B + (size_t)(colBase + lrow) * K + lcol;

    float acc[8][8];
    #pragma unroll
    for (int i = 0; i < 8; i++)
        #pragma unroll
        for (int j = 0; j < 8; j++) acc[i][j] = 0.0f;

    // prefetch first tile into registers
    float4 a0 = *(const float4*)(Ap);
    float4 a1 = *(const float4*)(Ap + 4);
    float4 b0 = *(const float4*)(Bp);
    float4 b1 = *(const float4*)(Bp + 4);

    const int NT = K / 16;
    for (int t = 0; t < NT; ++t) {
        // store current regs -> smem (A transposed to [k][m])
        As[lcol + 0][lrow] = a0.x; As[lcol + 1][lrow] = a0.y;
        As[lcol + 2][lrow] = a0.z; As[lcol + 3][lrow] = a0.w;
        As[lcol + 4][lrow] = a1.x; As[lcol + 5][lrow] = a1.y;
        As[lcol + 6][lrow] = a1.z; As[lcol + 7][lrow] = a1.w;
        Bs[lcol + 0][lrow] = b0.x; Bs[lcol + 1][lrow] = b0.y;
        Bs[lcol + 2][lrow] = b0.z; Bs[lcol + 3][lrow] = b0.w;
        Bs[lcol + 4][lrow] = b1.x; Bs[lcol + 5][lrow] = b1.y;
        Bs[lcol + 6][lrow] = b1.z; Bs[lcol + 7][lrow] = b1.w;
        __syncthreads();

        // prefetch next tile (global load latency hidden under compute)
        if (t + 1 < NT) {
            const float* Apn = Ap + (t + 1) * 16;
            const float* Bpn = Bp + (t + 1) * 16;
            a0 = *(const float4*)(Apn);
            a1 = *(const float4*)(Apn + 4);
            b0 = *(const float4*)(Bpn);
            b1 = *(const float4*)(Bpn + 4);
        }

        #pragma unroll
        for (int kk = 0; kk < 16; ++kk) {
            float ar[8], br[8];
            *(float4*)(ar)     = *(const float4*)&As[kk][ty * 8];
            *(float4*)(ar + 4) = *(const float4*)&As[kk][ty * 8 + 4];
            *(float4*)(br)     = *(const float4*)&Bs[kk][tx * 8];
            *(float4*)(br + 4) = *(const float4*)&Bs[kk][tx * 8 + 4];
            #pragma unroll
            for (int i = 0; i < 8; i++)
                #pragma unroll
                for (int j = 0; j < 8; j++)
                    acc[i][j] = fmaf(ar[i], br[j], acc[i][j]);
        }
        __syncthreads();
    }

    // ---------------- RMSNorm epilogue over the 128-col head ----------------
    if (normw != nullptr) {
        #pragma unroll
        for (int i = 0; i < 8; i++) {
            float ss = 0.0f;
            #pragma unroll
            for (int j = 0; j < 8; j++) ss = fmaf(acc[i][j], acc[i][j], ss);
            red[ty * 8 + i][tx] = ss;
        }
        __syncthreads();
        #pragma unroll
        for (int i = 0; i < 8; i++) {
            float tot = 0.0f;
            #pragma unroll
            for (int t = 0; t < 16; t++) tot += red[ty * 8 + i][t];
            float rinv = rsqrtf(tot * (1.0f / 128.0f) + EPSF);
            #pragma unroll
            for (int j = 0; j < 8; j++)
                acc[i][j] *= rinv * normw[tx * 8 + j];
        }
    }

    // ---------------- store ----------------
    #pragma unroll
    for (int i = 0; i < 8; i++) {
        size_t off = (size_t)(rowBase + ty * 8 + i) * N + colBase + tx * 8;
        float4 v0 = make_float4(acc[i][0], acc[i][1], acc[i][2], acc[i][3]);
        float4 v1 = make_float4(acc[i][4], acc[i][5], acc[i][6], acc[i][7]);
        *(float4*)(C + off)     = v0;
        *(float4*)(C + off + 4) = v1;
    }
}

// =================================================================================
// Flash attention (fp32, online softmax).
// Grid: (SEQ/64 q-tiles, B*H).  256 threads/block.
// Per key tile (64 keys): S = Q*K^T (scaled), online softmax, O += P*V.
// K and V share one SMEM buffer (loaded sequentially).
// =================================================================================
#define ATTN_SMEM_BYTES ((64*132*2 + 64*68 + 64*3 + 64*4) * 4)  /* 86784 B */

__global__ __launch_bounds__(256)
void attn_kernel()
{
    extern __shared__ float sm[];
    float* sQ    = sm;                 // [64][132]
    float* sKV   = sQ  + 64 * 132;     // [64][132]  (K then V)
    float* sP    = sKV + 64 * 132;     // [64][68]   (scores -> probs)
    float* sM    = sP  + 64 * 68;      // [64] running max
    float* sL    = sM  + 64;           // [64] running denom
    float* sC    = sL  + 64;           // [64] per-tile rescale factor
    float* sPart = sC  + 64;           // [64][4] partial row sums

    const int tid = threadIdx.x;
    const int qt  = blockIdx.x;        // 0..31
    const int bh  = blockIdx.y;        // 0..63
    const int b   = bh >> 4;
    const int h   = bh & 15;
    const int kvh = h >> 2;
    const int rg  = tid >> 4;          // 0..15 (4 rows each)
    const int cg  = tid & 15;          // 0..15
    const float scale = 0.0883883476483184f;  // 1/sqrt(128)

    // load Q tile (fold softmax scale in)
    const float* Qbase = g_Qn + (size_t)(b * SEQ + qt * 64) * DIMSZ + h * HD;
    for (int e = tid; e < 64 * 32; e += 256) {
        int r = e >> 5, c4 = (e & 31) * 4;
        float4 v = *(const float4*)(Qbase + (size_t)r * DIMSZ + c4);
        v.x *= scale; v.y *= scale; v.z *= scale; v.w *= scale;
        *(float4*)(sQ + r * 132 + c4) = v;
    }
    if (tid < 64) { sM[tid] = -1e30f; sL[tid] = 0.0f; }

    float o[4][8] = {};

    const float* Kbase = g_Kn + (size_t)(b * SEQ) * KVW + kvh * HD;
    const float* Vbase = g_Vn + (size_t)(b * SEQ) * KVW + kvh * HD;

    for (int kt = 0; kt < SEQ / 64; ++kt) {
        // ---- load K tile ----
        for (int e = tid; e < 64 * 32; e += 256) {
            int r = e >> 5, c4 = (e & 31) * 4;
            *(float4*)(sKV + r * 132 + c4) =
                *(const float4*)(Kbase + (size_t)(kt * 64 + r) * KVW + c4);
        }
        __syncthreads();

        // ---- scores: rows rg*4+i, cols cg*4+j ----
        float s[4][4] = {};
        #pragma unroll 4
        for (int k4 = 0; k4 < 32; ++k4) {
            float4 qv[4], kk[4];
            #pragma unroll
            for (int i = 0; i < 4; i++)
                qv[i] = *(const float4*)(sQ + (rg * 4 + i) * 132 + k4 * 4);
            #pragma unroll
            for (int j = 0; j < 4; j++)
                kk[j] = *(const float4*)(sKV + (cg * 4 + j) * 132 + k4 * 4);
            #pragma unroll
            for (int i = 0; i < 4; i++)
                #pragma unroll
                for (int j = 0; j < 4; j++) {
                    s[i][j] = fmaf(qv[i].x, kk[j].x, s[i][j]);
                    s[i][j] = fmaf(qv[i].y, kk[j].y, s[i][j]);
                    s[i][j] = fmaf(qv[i].z, kk[j].z, s[i][j]);
                    s[i][j] = fmaf(qv[i].w, kk[j].w, s[i][j]);
                }
        }
        #pragma unroll
        for (int i = 0; i < 4; i++)
            #pragma unroll
            for (int j = 0; j < 4; j++)
                sP[(rg * 4 + i) * 68 + cg * 4 + j] = s[i][j];
        __syncthreads();

        // ---- load V tile (overwrites K; scores already in sP) + row max ----
        for (int e = tid; e < 64 * 32; e += 256) {
            int r = e >> 5, c4 = (e & 31) * 4;
            *(float4*)(sKV + r * 132 + c4) =
                *(const float4*)(Vbase + (size_t)(kt * 64 + r) * KVW + c4);
        }
        if (tid < 64) {
            const float* row = sP + tid * 68;
            float m0 = row[0], m1 = row[1], m2 = row[2], m3 = row[3];
            #pragma unroll
            for (int c = 4; c < 64; c += 4) {
                m0 = fmaxf(m0, row[c + 0]);
                m1 = fmaxf(m1, row[c + 1]);
                m2 = fmaxf(m2, row[c + 2]);
                m3 = fmaxf(m3, row[c + 3]);
            }
            float mx = fmaxf(fmaxf(m0, m1), fmaxf(m2, m3));
            float mo = sM[tid];
            float mn = fmaxf(mo, mx);
            sM[tid] = mn;
            sC[tid] = __expf(mo - mn);
        }
        __syncthreads();

        // ---- exp (distributed over all 256 threads) + partial sums ----
        {
            int r = tid >> 2, c0 = (tid & 3) * 16;
            float mn = sM[r];
            float* row = sP + r * 68 + c0;
            float ps = 0.0f;
            #pragma unroll
            for (int j = 0; j < 16; j++) {
                float p = __expf(row[j] - mn);
                row[j] = p;
                ps += p;
            }
            sPart[r * 4 + (tid & 3)] = ps;
        }
        __syncthreads();

        // ---- update denom; rescale O; accumulate P*V ----
        if (tid < 64)
            sL[tid] = sL[tid] * sC[tid] +
                      sPart[tid * 4] + sPart[tid * 4 + 1] +
                      sPart[tid * 4 + 2] + sPart[tid * 4 + 3];

        #pragma unroll
        for (int i = 0; i < 4; i++) {
            float cr = sC[rg * 4 + i];
            #pragma unroll
            for (int j = 0; j < 8; j++) o[i][j] *= cr;
        }

        #pragma unroll 4
        for (int k = 0; k < 64; ++k) {
            float4 v0 = *(const float4*)(sKV + k * 132 + cg * 4);
            float4 v1 = *(const float4*)(sKV + k * 132 + 64 + cg * 4);
            #pragma unroll
            for (int i = 0; i < 4; i++) {
                float p = sP[(rg * 4 + i) * 68 + k];
                o[i][0] = fmaf(p, v0.x, o[i][0]);
                o[i][1] = fmaf(p, v0.y, o[i][1]);
                o[i][2] = fmaf(p, v0.z, o[i][2]);
                o[i][3] = fmaf(p, v0.w, o[i][3]);
                o[i][4] = fmaf(p, v1.x, o[i][4]);
                o[i][5] = fmaf(p, v1.y, o[i][5]);
                o[i][6] = fmaf(p, v1.z, o[i][6]);
                o[i][7] = fmaf(p, v1.w, o[i][7]);
            }
        }
        __syncthreads();
    }

    // ---- epilogue: divide by denom, store (cols cg*4 and cg*4+64) ----
    float* Obase = g_AO + (size_t)(b * SEQ + qt * 64) * DIMSZ + h * HD;
    #pragma unroll
    for (int i = 0; i < 4; i++) {
        int r = rg * 4 + i;
        float inv = 1.0f / sL[r];
        float4 v0 = make_float4(o[i][0] * inv, o[i][1] * inv, o[i][2] * inv, o[i][3] * inv);
        float4 v1 = make_float4(o[i][4] * inv, o[i][5] * inv, o[i][6] * inv, o[i][7] * inv);
        *(float4*)(Obase + (size_t)r * DIMSZ + cg * 4)      = v0;
        *(float4*)(Obase + (size_t)r * DIMSZ + 64 + cg * 4) = v1;
    }
}

// =================================================================================
// Host launcher
// =================================================================================
extern "C" void kernel_launch(void* const* d_in, const int* in_sizes, int n_in,
                              void* d_out, int out_size)
{
    (void)in_sizes; (void)n_in; (void)out_size;
    const float* query = (const float*)d_in[0];
    const float* key   = (const float*)d_in[1];
    const float* value = (const float*)d_in[2];
    const float* Wq    = (const float*)d_in[3];
    const float* Wk    = (const float*)d_in[4];
    const float* Wv    = (const float*)d_in[5];
    const float* Wo    = (const float*)d_in[6];
    const float* nqw   = (const float*)d_in[7];
    const float* nkw   = (const float*)d_in[8];
    float* out = (float*)d_out;

    void *qn, *kn, *vn, *ao;
    cudaGetSymbolAddress(&qn, g_Qn);
    cudaGetSymbolAddress(&kn, g_Kn);
    cudaGetSymbolAddress(&vn, g_Vn);
    cudaGetSymbolAddress(&ao, g_AO);

    cudaFuncSetAttribute(attn_kernel,
                         cudaFuncAttributeMaxDynamicSharedMemorySize,
                         ATTN_SMEM_BYTES);

    dim3 blk(256);
    // Q projection + per-head RMSNorm
    sgemm_nt<<<dim3(DIMSZ / 128, MROWS / 128), blk>>>(query, Wq, (float*)qn, DIMSZ, DIMSZ, nqw);
    // K projection + per-head RMSNorm
    sgemm_nt<<<dim3(KVW / 128, MROWS / 128), blk>>>(key, Wk, (float*)kn, KVW, DIMSZ, nkw);
    // V projection
    sgemm_nt<<<dim3(KVW / 128, MROWS / 128), blk>>>(value, Wv, (float*)vn, KVW, DIMSZ, nullptr);
    // attention
    attn_kernel<<<dim3(SEQ / 64, BSZ * NHEADS), blk, ATTN_SMEM_BYTES>>>();
    // output projection
    sgemm_nt<<<dim3(DIMSZ / 128, MROWS / 128), blk>>>((const float*)ao, Wo, out, DIMSZ, DIMSZ, nullptr);
}

// round 7
// speedup vs baseline: 3.1147x; 3.1147x over previous
#include <cuda_runtime.h>
#include <cstdint>

#define DIMSZ   2048
#define HD      128
#define NHEADS  16
#define NKV     4
#define BSZ     4
#define SEQ     2048
#define MROWS   (BSZ*SEQ)      /* 8192 */
#define KVW     (NKV*HD)       /* 512  */
#define EPSF    1e-6f

// ---------------- scratch (static device globals; no allocation) ----------------
__device__ float g_Qn[(size_t)MROWS * DIMSZ];   // 64 MB
__device__ float g_Kn[(size_t)MROWS * KVW];     // 16 MB
__device__ float g_Vn[(size_t)MROWS * KVW];     // 16 MB
__device__ float g_AO[(size_t)MROWS * DIMSZ];   // 64 MB

// ---------------- tf32 helpers ----------------
__device__ __forceinline__ uint32_t f2tf(float x) {
    uint32_t u; asm("cvt.rna.tf32.f32 %0, %1;" : "=r"(u) : "f"(x)); return u;
}
// D(16x8) += A(16x8,row) * B(8x8,col);  A: 4 regs, B: 2 regs, D: 4 f32
__device__ __forceinline__ void mma8(float* d, const uint32_t* a, const uint32_t* b) {
    asm volatile(
        "mma.sync.aligned.m16n8k8.row.col.f32.tf32.tf32.f32 "
        "{%0,%1,%2,%3}, {%4,%5,%6,%7}, {%8,%9}, {%0,%1,%2,%3};"
        : "+f"(d[0]), "+f"(d[1]), "+f"(d[2]), "+f"(d[3])
        : "r"(a[0]), "r"(a[1]), "r"(a[2]), "r"(a[3]), "r"(b[0]), "r"(b[1]));
}

// =================================================================================
// C[M,N] = A[M,K] @ B[N,K]^T, tf32 tensor core. BM=BN=128, BK=16, 256 thr, 8 warps.
// Warp tile 64x32 (2x4 warp grid), 4x4 m16n8k8 MMA tiles per warp.
// Optional RMSNorm epilogue over each 128-col block (== one head for Q/K proj).
// SMEM stride 20 words -> conflict-free fragment loads.
// =================================================================================
#define GST 20
__global__ __launch_bounds__(256)
void gemm_tf32(const float* __restrict__ A, const float* __restrict__ B,
               float* __restrict__ C, int N, int K,
               const float* __restrict__ normw)
{
    __shared__ uint32_t As[128 * GST];   // [m][k], tf32 bits
    __shared__ uint32_t Bs[128 * GST];   // [n][k], tf32 bits
    __shared__ float    red[128 * 4];

    const int tid  = threadIdx.x;
    const int lane = tid & 31;
    const int wid  = tid >> 5;
    const int g    = lane >> 2;          // 0..7
    const int t4   = lane & 3;           // 0..3
    const int wm   = wid & 1;            // 0..1
    const int wn   = wid >> 1;           // 0..3
    const int rowBase = blockIdx.y * 128;
    const int colBase = blockIdx.x * 128;

    const int lrow = tid >> 1;           // 0..127
    const int lcol = (tid & 1) * 8;      // 0 or 8
    const float* Ap = A + (size_t)(rowBase + lrow) * K + lcol;
    const float* Bp = B + (size_t)(colBase + lrow) * K + lcol;

    float d[4][4][4];
    #pragma unroll
    for (int i = 0; i < 4; i++)
        #pragma unroll
        for (int j = 0; j < 4; j++)
            #pragma unroll
            for (int c = 0; c < 4; c++) d[i][j][c] = 0.0f;

    float4 a0 = *(const float4*)(Ap);
    float4 a1 = *(const float4*)(Ap + 4);
    float4 b0 = *(const float4*)(Bp);
    float4 b1 = *(const float4*)(Bp + 4);

    const int NT = K / 16;
    for (int t = 0; t < NT; ++t) {
        *(uint4*)(As + lrow * GST + lcol)     = make_uint4(f2tf(a0.x), f2tf(a0.y), f2tf(a0.z), f2tf(a0.w));
        *(uint4*)(As + lrow * GST + lcol + 4) = make_uint4(f2tf(a1.x), f2tf(a1.y), f2tf(a1.z), f2tf(a1.w));
        *(uint4*)(Bs + lrow * GST + lcol)     = make_uint4(f2tf(b0.x), f2tf(b0.y), f2tf(b0.z), f2tf(b0.w));
        *(uint4*)(Bs + lrow * GST + lcol + 4) = make_uint4(f2tf(b1.x), f2tf(b1.y), f2tf(b1.z), f2tf(b1.w));
        __syncthreads();

        if (t + 1 < NT) {
            const float* Apn = Ap + (t + 1) * 16;
            const float* Bpn = Bp + (t + 1) * 16;
            a0 = *(const float4*)(Apn);
            a1 = *(const float4*)(Apn + 4);
            b0 = *(const float4*)(Bpn);
            b1 = *(const float4*)(Bpn + 4);
        }

        #pragma unroll
        for (int k8 = 0; k8 < 16; k8 += 8) {
            uint32_t af[4][4], bf[4][2];
            #pragma unroll
            for (int mt = 0; mt < 4; mt++) {
                const uint32_t* p = As + (wm * 64 + mt * 16 + g) * GST + k8 + t4;
                af[mt][0] = p[0];
                af[mt][1] = p[8 * GST];
                af[mt][2] = p[4];
                af[mt][3] = p[8 * GST + 4];
            }
            #pragma unroll
            for (int nt = 0; nt < 4; nt++) {
                const uint32_t* p = Bs + (wn * 32 + nt * 8 + g) * GST + k8 + t4;
                bf[nt][0] = p[0];
                bf[nt][1] = p[4];
            }
            #pragma unroll
            for (int mt = 0; mt < 4; mt++)
                #pragma unroll
                for (int nt = 0; nt < 4; nt++)
                    mma8(d[mt][nt], af[mt], bf[nt]);
        }
        __syncthreads();
    }

    // ---------------- RMSNorm epilogue (per-head = per 128-col block) ----------------
    if (normw != nullptr) {
        #pragma unroll
        for (int mt = 0; mt < 4; mt++) {
            float s0 = 0.0f, s1 = 0.0f;
            #pragma unroll
            for (int nt = 0; nt < 4; nt++) {
                s0 = fmaf(d[mt][nt][0], d[mt][nt][0], s0);
                s0 = fmaf(d[mt][nt][1], d[mt][nt][1], s0);
                s1 = fmaf(d[mt][nt][2], d[mt][nt][2], s1);
                s1 = fmaf(d[mt][nt][3], d[mt][nt][3], s1);
            }
            s0 += __shfl_xor_sync(0xffffffffu, s0, 1);
            s0 += __shfl_xor_sync(0xffffffffu, s0, 2);
            s1 += __shfl_xor_sync(0xffffffffu, s1, 1);
            s1 += __shfl_xor_sync(0xffffffffu, s1, 2);
            if (t4 == 0) {
                red[(wm * 64 + mt * 16 + g) * 4 + wn]     = s0;
                red[(wm * 64 + mt * 16 + g + 8) * 4 + wn] = s1;
            }
        }
        __syncthreads();
        #pragma unroll
        for (int mt = 0; mt < 4; mt++) {
            int r0 = wm * 64 + mt * 16 + g;
            float tt0 = red[r0 * 4] + red[r0 * 4 + 1] + red[r0 * 4 + 2] + red[r0 * 4 + 3];
            float tt1 = red[(r0 + 8) * 4] + red[(r0 + 8) * 4 + 1] + red[(r0 + 8) * 4 + 2] + red[(r0 + 8) * 4 + 3];
            float ri0 = rsqrtf(tt0 * (1.0f / 128.0f) + EPSF);
            float ri1 = rsqrtf(tt1 * (1.0f / 128.0f) + EPSF);
            #pragma unroll
            for (int nt = 0; nt < 4; nt++) {
                int c = wn * 32 + nt * 8 + 2 * t4;
                float w0 = normw[c], w1 = normw[c + 1];
                d[mt][nt][0] *= ri0 * w0; d[mt][nt][1] *= ri0 * w1;
                d[mt][nt][2] *= ri1 * w0; d[mt][nt][3] *= ri1 * w1;
            }
        }
    }

    // ---------------- store ----------------
    #pragma unroll
    for (int mt = 0; mt < 4; mt++) {
        int r = rowBase + wm * 64 + mt * 16 + g;
        #pragma unroll
        for (int nt = 0; nt < 4; nt++) {
            int c = colBase + wn * 32 + nt * 8 + 2 * t4;
            *(float2*)(C + (size_t)r * N + c)       = make_float2(d[mt][nt][0], d[mt][nt][1]);
            *(float2*)(C + (size_t)(r + 8) * N + c) = make_float2(d[mt][nt][2], d[mt][nt][3]);
        }
    }
}

// =================================================================================
// Flash attention, tf32 tensor core, online softmax.
// 64-query x 64-key tiles, 256 threads (8 warps).
//  scores: 2x4 warp grid, warp tile 32x16 (2x2 MMA tiles), K=128
//  PV:     2x4 warp grid, warp tile 32x32 (2x4 MMA tiles), K=64
// K stride 132, V stride 136, P stride 68 -> conflict-free fragment loads.
// =================================================================================
#define ATTN_SMEM ((64*132 + 64*136 + 64*68 + 64*3 + 64*4) * 4)  /* 87808 B */

__global__ __launch_bounds__(256)
void attn_tf32()
{
    extern __shared__ float sm[];
    float* sQ    = sm;                 // [64][132] tf32 bits (scale folded)
    float* sKV   = sQ  + 64 * 132;     // K: [64][132], V: [64][136] (shared buffer)
    float* sP    = sKV + 64 * 136;     // [64][68] scores(f32) -> probs(tf32 bits)
    float* sM    = sP  + 64 * 68;
    float* sL    = sM  + 64;
    float* sC    = sL  + 64;
    float* sPart = sC  + 64;           // [64][4]

    uint32_t* sQu = (uint32_t*)sQ;
    uint32_t* sKu = (uint32_t*)sKV;
    uint32_t* sVu = (uint32_t*)sKV;
    uint32_t* sPu = (uint32_t*)sP;

    const int tid  = threadIdx.x;
    const int lane = tid & 31;
    const int wid  = tid >> 5;
    const int g    = lane >> 2;
    const int t4   = lane & 3;
    const int wm   = wid & 1;
    const int wn   = wid >> 1;
    const int qt   = blockIdx.x;       // 0..31
    const int bh   = blockIdx.y;       // 0..63
    const int b    = bh >> 4;
    const int h    = bh & 15;
    const int kvh  = h >> 2;
    const float scale = 0.0883883476483184f;   // 1/sqrt(128)

    // load Q tile (scale folded, cvt to tf32)
    const float* Qbase = g_Qn + (size_t)(b * SEQ + qt * 64) * DIMSZ + h * HD;
    for (int e = tid; e < 64 * 32; e += 256) {
        int r = e >> 5, c4 = (e & 31) * 4;
        float4 v = *(const float4*)(Qbase + (size_t)r * DIMSZ + c4);
        *(uint4*)(sQu + r * 132 + c4) =
            make_uint4(f2tf(v.x * scale), f2tf(v.y * scale), f2tf(v.z * scale), f2tf(v.w * scale));
    }
    if (tid < 64) { sM[tid] = -1e30f; sL[tid] = 0.0f; }

    float o[2][4][4];
    #pragma unroll
    for (int i = 0; i < 2; i++)
        #pragma unroll
        for (int j = 0; j < 4; j++)
            #pragma unroll
            for (int c = 0; c < 4; c++) o[i][j][c] = 0.0f;

    const float* Kb = g_Kn + (size_t)(b * SEQ) * KVW + kvh * HD;
    const float* Vb = g_Vn + (size_t)(b * SEQ) * KVW + kvh * HD;

    for (int kt = 0; kt < SEQ / 64; ++kt) {
        // ---- load K tile (tf32) ----
        for (int e = tid; e < 64 * 32; e += 256) {
            int r = e >> 5, c4 = (e & 31) * 4;
            float4 v = *(const float4*)(Kb + (size_t)(kt * 64 + r) * KVW + c4);
            *(uint4*)(sKu + r * 132 + c4) = make_uint4(f2tf(v.x), f2tf(v.y), f2tf(v.z), f2tf(v.w));
        }
        __syncthreads();

        // ---- scores S = Q K^T via MMA ----
        float s[2][2][4];
        #pragma unroll
        for (int i = 0; i < 2; i++)
            #pragma unroll
            for (int j = 0; j < 2; j++)
                #pragma unroll
                for (int c = 0; c < 4; c++) s[i][j][c] = 0.0f;

        #pragma unroll
        for (int k8 = 0; k8 < 128; k8 += 8) {
            uint32_t af[2][4], bf[2][2];
            #pragma unroll
            for (int mt = 0; mt < 2; mt++) {
                const uint32_t* p = sQu + (wm * 32 + mt * 16 + g) * 132 + k8 + t4;
                af[mt][0] = p[0];
                af[mt][1] = p[8 * 132];
                af[mt][2] = p[4];
                af[mt][3] = p[8 * 132 + 4];
            }
            #pragma unroll
            for (int nt = 0; nt < 2; nt++) {
                const uint32_t* p = sKu + (wn * 16 + nt * 8 + g) * 132 + k8 + t4;
                bf[nt][0] = p[0];
                bf[nt][1] = p[4];
            }
            #pragma unroll
            for (int mt = 0; mt < 2; mt++)
                #pragma unroll
                for (int nt = 0; nt < 2; nt++)
                    mma8(s[mt][nt], af[mt], bf[nt]);
        }
        #pragma unroll
        for (int mt = 0; mt < 2; mt++)
            #pragma unroll
            for (int nt = 0; nt < 2; nt++) {
                int r = wm * 32 + mt * 16 + g;
                int c = wn * 16 + nt * 8 + 2 * t4;
                *(float2*)(sP + r * 68 + c)       = make_float2(s[mt][nt][0], s[mt][nt][1]);
                *(float2*)(sP + (r + 8) * 68 + c) = make_float2(s[mt][nt][2], s[mt][nt][3]);
            }
        __syncthreads();

        // ---- load V tile (overwrites K, stride 136) + row max ----
        for (int e = tid; e < 64 * 32; e += 256) {
            int r = e >> 5, c4 = (e & 31) * 4;
            float4 v = *(const float4*)(Vb + (size_t)(kt * 64 + r) * KVW + c4);
            *(uint4*)(sVu + r * 136 + c4) = make_uint4(f2tf(v.x), f2tf(v.y), f2tf(v.z), f2tf(v.w));
        }
        if (tid < 64) {
            const float* row = sP + tid * 68;
            float m0 = row[0], m1 = row[1], m2 = row[2], m3 = row[3];
            #pragma unroll
            for (int c = 4; c < 64; c += 4) {
                m0 = fmaxf(m0, row[c + 0]);
                m1 = fmaxf(m1, row[c + 1]);
                m2 = fmaxf(m2, row[c + 2]);
                m3 = fmaxf(m3, row[c + 3]);
            }
            float mx = fmaxf(fmaxf(m0, m1), fmaxf(m2, m3));
            float mo = sM[tid];
            float mn = fmaxf(mo, mx);
            sM[tid] = mn;
            sC[tid] = __expf(mo - mn);
        }
        __syncthreads();

        // ---- exp (256 threads) + partial sums; store probs pre-cvt'd to tf32 ----
        {
            int r = tid >> 2, c0 = (tid & 3) * 16;
            float mn = sM[r];
            float* row = sP + r * 68 + c0;
            float ps = 0.0f;
            #pragma unroll
            for (int j = 0; j < 16; j++) {
                float p = __expf(row[j] - mn);
                ps += p;
                row[j] = __uint_as_float(f2tf(p));
            }
            sPart[r * 4 + (tid & 3)] = ps;
        }
        __syncthreads();

        // ---- denom update; rescale O; PV via MMA ----
        if (tid < 64)
            sL[tid] = sL[tid] * sC[tid] +
                      sPart[tid * 4] + sPart[tid * 4 + 1] +
                      sPart[tid * 4 + 2] + sPart[tid * 4 + 3];

        #pragma unroll
        for (int mt = 0; mt < 2; mt++) {
            float cr0 = sC[wm * 32 + mt * 16 + g];
            float cr1 = sC[wm * 32 + mt * 16 + g + 8];
            #pragma unroll
            for (int nt = 0; nt < 4; nt++) {
                o[mt][nt][0] *= cr0; o[mt][nt][1] *= cr0;
                o[mt][nt][2] *= cr1; o[mt][nt][3] *= cr1;
            }
        }

        #pragma unroll
        for (int k8 = 0; k8 < 64; k8 += 8) {
            uint32_t af[2][4], bf[4][2];
            #pragma unroll
            for (int mt = 0; mt < 2; mt++) {
                const uint32_t* p = sPu + (wm * 32 + mt * 16 + g) * 68 + k8 + t4;
                af[mt][0] = p[0];
                af[mt][1] = p[8 * 68];
                af[mt][2] = p[4];
                af[mt][3] = p[8 * 68 + 4];
            }
            #pragma unroll
            for (int nt = 0; nt < 4; nt++) {
                const uint32_t* p = sVu + (size_t)(k8 + t4) * 136 + wn * 32 + nt * 8 + g;
                bf[nt][0] = p[0];
                bf[nt][1] = p[4 * 136];
            }
            #pragma unroll
            for (int mt = 0; mt < 2; mt++)
                #pragma unroll
                for (int nt = 0; nt < 4; nt++)
                    mma8(o[mt][nt], af[mt], bf[nt]);
        }
        __syncthreads();
    }

    // ---- epilogue: divide by denom, store ----
    float* Obase = g_AO + (size_t)(b * SEQ + qt * 64) * DIMSZ + h * HD;
    #pragma unroll
    for (int mt = 0; mt < 2; mt++) {
        int r = wm * 32 + mt * 16 + g;
        float i0 = 1.0f / sL[r];
        float i1 = 1.0f / sL[r + 8];
        #pragma unroll
        for (int nt = 0; nt < 4; nt++) {
            int c = wn * 32 + nt * 8 + 2 * t4;
            *(float2*)(Obase + (size_t)r * DIMSZ + c) =
                make_float2(o[mt][nt][0] * i0, o[mt][nt][1] * i0);
            *(float2*)(Obase + (size_t)(r + 8) * DIMSZ + c) =
                make_float2(o[mt][nt][2] * i1, o[mt][nt][3] * i1);
        }
    }
}

// =================================================================================
// Host launcher
// =================================================================================
extern "C" void kernel_launch(void* const* d_in, const int* in_sizes, int n_in,
                              void* d_out, int out_size)
{
    (void)in_sizes; (void)n_in; (void)out_size;
    const float* query = (const float*)d_in[0];
    const float* key   = (const float*)d_in[1];
    const float* value = (const float*)d_in[2];
    const float* Wq    = (const float*)d_in[3];
    const float* Wk    = (const float*)d_in[4];
    const float* Wv    = (const float*)d_in[5];
    const float* Wo    = (const float*)d_in[6];
    const float* nqw   = (const float*)d_in[7];
    const float* nkw   = (const float*)d_in[8];
    float* out = (float*)d_out;

    void *qn, *kn, *vn, *ao;
    cudaGetSymbolAddress(&qn, g_Qn);
    cudaGetSymbolAddress(&kn, g_Kn);
    cudaGetSymbolAddress(&vn, g_Vn);
    cudaGetSymbolAddress(&ao, g_AO);

    cudaFuncSetAttribute(attn_tf32,
                         cudaFuncAttributeMaxDynamicSharedMemorySize,
                         ATTN_SMEM);

    dim3 blk(256);
    // Q projection + per-head RMSNorm
    gemm_tf32<<<dim3(DIMSZ / 128, MROWS / 128), blk>>>(query, Wq, (float*)qn, DIMSZ, DIMSZ, nqw);
    // K projection + per-head RMSNorm
    gemm_tf32<<<dim3(KVW / 128, MROWS / 128), blk>>>(key, Wk, (float*)kn, KVW, DIMSZ, nkw);
    // V projection
    gemm_tf32<<<dim3(KVW / 128, MROWS / 128), blk>>>(value, Wv, (float*)vn, KVW, DIMSZ, nullptr);
    // attention
    attn_tf32<<<dim3(SEQ / 64, BSZ * NHEADS), blk, ATTN_SMEM>>>();
    // output projection
    gemm_tf32<<<dim3(DIMSZ / 128, MROWS / 128), blk>>>((const float*)ao, Wo, out, DIMSZ, DIMSZ, nullptr);
}